// round 1
// baseline (speedup 1.0000x reference)
#include <cuda_runtime.h>
#include <cstdint>

#define BQ 4
#define TT 4096
#define DD 1024
#define MM (BQ * TT)          // 16384 rows
#define NCH 64                // chunks along T
#define CHUNK 64              // T / NCH

// ---- scratch (allocation-free rule: __device__ globals) ----
__device__ float g_y1[(size_t)MM * DD];   // x@Wz + bz   (pre-sigmoid)
__device__ float g_y2[(size_t)MM * DD];   // x@Wh + bh
__device__ float g_cA[BQ * NCH * DD];     // per-chunk composed A
__device__ float g_cB[BQ * NCH * DD];     // per-chunk composed B
__device__ float g_cH[BQ * NCH * DD];     // h at chunk start

__device__ __forceinline__ uint32_t f2tf32(float x) {
    uint32_t r;
    asm("cvt.rna.tf32.f32 %0, %1;" : "=r"(r) : "f"(x));
    return r;
}

__device__ __forceinline__ void mma_tf32(float c[4], const uint32_t a[4], const uint32_t b[2]) {
    asm volatile(
        "mma.sync.aligned.m16n8k8.row.col.f32.tf32.tf32.f32 "
        "{%0,%1,%2,%3}, {%4,%5,%6,%7}, {%8,%9}, {%0,%1,%2,%3};\n"
        : "+f"(c[0]), "+f"(c[1]), "+f"(c[2]), "+f"(c[3])
        : "r"(a[0]), "r"(a[1]), "r"(a[2]), "r"(a[3]),
          "r"(b[0]), "r"(b[1]));
}

// ============================================================
// GEMM: Y = X @ W + bias.  X row-major [M,K], W row-major [K,N].
// Block tile 128x128, K-tile 32. 8 warps = 2(m) x 4(n), warp tile 64x32.
// blockIdx.z selects (Wz,bz)->g_y1 or (Wh,bh)->g_y2.
// ============================================================
__global__ __launch_bounds__(256, 2)
void gemm_tf32_kernel(const float* __restrict__ X,
                      const float* __restrict__ Wz, const float* __restrict__ bz,
                      const float* __restrict__ Wh, const float* __restrict__ bh)
{
    __shared__ uint32_t As[128][36];   // [m][k], pad 36 -> conflict-free frag loads
    __shared__ uint32_t Bs[32][132];   // [k][n], pad 132

    const float* __restrict__ W    = blockIdx.z ? Wh : Wz;
    const float* __restrict__ bias = blockIdx.z ? bh : bz;
    float* __restrict__ Y          = blockIdx.z ? g_y2 : g_y1;

    const int tid  = threadIdx.x;
    const int warp = tid >> 5, lane = tid & 31;
    const int wm = warp >> 2, wn = warp & 3;    // 2 x 4 warp grid
    const int g = lane >> 2, t = lane & 3;      // groupID / threadInGroup

    const int bm = blockIdx.y;  // M / 128
    const int bn = blockIdx.x;  // N / 128

    float acc[4][4][4];
    #pragma unroll
    for (int i = 0; i < 4; i++)
        #pragma unroll
        for (int j = 0; j < 4; j++)
            #pragma unroll
            for (int k = 0; k < 4; k++) acc[i][j][k] = 0.f;

    const int ar = tid >> 3, ac4 = tid & 7;     // A loader: 32 rows/pass, 8 float4 per row
    const int br = tid >> 5, bc4 = tid & 31;    // B loader: 8 rows/pass, 32 float4 per row

    for (int kt = 0; kt < DD / 32; kt++) {
        // ---- load A tile (128 x 32) ----
        #pragma unroll
        for (int p = 0; p < 4; p++) {
            int row = p * 32 + ar;
            const float4 v = *(const float4*)&X[(size_t)(bm * 128 + row) * DD + kt * 32 + ac4 * 4];
            uint4 u = make_uint4(f2tf32(v.x), f2tf32(v.y), f2tf32(v.z), f2tf32(v.w));
            *(uint4*)&As[row][ac4 * 4] = u;
        }
        // ---- load B tile (32 x 128) ----
        #pragma unroll
        for (int p = 0; p < 4; p++) {
            int row = p * 8 + br;
            const float4 v = *(const float4*)&W[(size_t)(kt * 32 + row) * DD + bn * 128 + bc4 * 4];
            uint4 u = make_uint4(f2tf32(v.x), f2tf32(v.y), f2tf32(v.z), f2tf32(v.w));
            *(uint4*)&Bs[row][bc4 * 4] = u;
        }
        __syncthreads();

        #pragma unroll
        for (int ks = 0; ks < 4; ks++) {
            uint32_t afr[4][4], bfr[4][2];
            const int kk = ks * 8 + t;
            #pragma unroll
            for (int mf = 0; mf < 4; mf++) {
                int m = wm * 64 + mf * 16 + g;
                afr[mf][0] = As[m][kk];
                afr[mf][1] = As[m + 8][kk];
                afr[mf][2] = As[m][kk + 4];
                afr[mf][3] = As[m + 8][kk + 4];
            }
            #pragma unroll
            for (int nf = 0; nf < 4; nf++) {
                int n = wn * 32 + nf * 8 + g;
                bfr[nf][0] = Bs[kk][n];
                bfr[nf][1] = Bs[kk + 4][n];
            }
            #pragma unroll
            for (int mf = 0; mf < 4; mf++)
                #pragma unroll
                for (int nf = 0; nf < 4; nf++)
                    mma_tf32(acc[mf][nf], afr[mf], bfr[nf]);
        }
        __syncthreads();
    }

    // ---- epilogue: + bias, store fp32 ----
    #pragma unroll
    for (int mf = 0; mf < 4; mf++) {
        int row0 = bm * 128 + wm * 64 + mf * 16 + g;
        #pragma unroll
        for (int nf = 0; nf < 4; nf++) {
            int col = bn * 128 + wn * 32 + nf * 8 + 2 * t;
            float b0 = bias[col], b1 = bias[col + 1];
            float2 v01 = make_float2(acc[mf][nf][0] + b0, acc[mf][nf][1] + b1);
            float2 v23 = make_float2(acc[mf][nf][2] + b0, acc[mf][nf][3] + b1);
            *(float2*)&Y[(size_t)row0 * DD + col] = v01;
            *(float2*)&Y[(size_t)(row0 + 8) * DD + col] = v23;
        }
    }
}

// ============================================================
// Scan phase 1: per-chunk composition. h_end = A*h_start + B.
// grid (D/128, NCH, B), 128 threads; thread handles one channel d.
// All loads coalesced (d-contiguous).
// ============================================================
__global__ void scan_reduce_kernel()
{
    const int d = blockIdx.x * 128 + threadIdx.x;
    const int c = blockIdx.y, b = blockIdx.z;
    size_t base = ((size_t)(b * TT + c * CHUNK)) * DD + d;
    float A = 1.f, Bc = 0.f;
    #pragma unroll 4
    for (int i = 0; i < CHUNK; i++) {
        float y1 = g_y1[base], y2 = g_y2[base];
        float z = 1.f / (1.f + __expf(-y1));
        float a = 1.f - z;
        Bc = fmaf(a, Bc, z * y2);
        A *= a;
        base += DD;
    }
    const int idx = (b * NCH + c) * DD + d;
    g_cA[idx] = A;
    g_cB[idx] = Bc;
}

// ============================================================
// Scan phase 2: serial scan over the 64 chunk carries per channel.
// grid (D/128, B), 128 threads. Tiny (2 MB traffic).
// ============================================================
__global__ void scan_carry_kernel()
{
    const int d = blockIdx.x * 128 + threadIdx.x;
    const int b = blockIdx.y;
    float h = 0.f;
    #pragma unroll
    for (int c = 0; c < NCH; c++) {
        const int idx = (b * NCH + c) * DD + d;
        g_cH[idx] = h;                      // h at START of chunk c
        h = fmaf(g_cA[idx], h, g_cB[idx]);  // h at end of chunk c
    }
}

// ============================================================
// Scan phase 3: rescan each chunk from its carry, write output.
// ============================================================
__global__ void scan_apply_kernel(float* __restrict__ out)
{
    const int d = blockIdx.x * 128 + threadIdx.x;
    const int c = blockIdx.y, b = blockIdx.z;
    size_t base = ((size_t)(b * TT + c * CHUNK)) * DD + d;
    float h = g_cH[(b * NCH + c) * DD + d];
    #pragma unroll 4
    for (int i = 0; i < CHUNK; i++) {
        float y1 = g_y1[base], y2 = g_y2[base];
        float z = 1.f / (1.f + __expf(-y1));
        h = fmaf(1.f - z, h, z * y2);
        out[base] = h;
        base += DD;
    }
}

// ============================================================
extern "C" void kernel_launch(void* const* d_in, const int* in_sizes, int n_in,
                              void* d_out, int out_size)
{
    const float* x  = (const float*)d_in[0];
    const float* Wz = (const float*)d_in[1];
    const float* bz = (const float*)d_in[2];
    const float* Wh = (const float*)d_in[3];
    const float* bh = (const float*)d_in[4];
    float* out = (float*)d_out;

    // Two GEMMs in one grid (z dim selects weight/bias/output).
    gemm_tf32_kernel<<<dim3(DD / 128, MM / 128, 2), 256>>>(x, Wz, bz, Wh, bh);
    // Chunked associative scan.
    scan_reduce_kernel<<<dim3(DD / 128, NCH, BQ), 128>>>();
    scan_carry_kernel<<<dim3(DD / 128, BQ), 128>>>();
    scan_apply_kernel<<<dim3(DD / 128, NCH, BQ), 128>>>(out);
}